// round 8
// baseline (speedup 1.0000x reference)
#include <cuda_runtime.h>
#include <cstdint>

// image [B=4, C=1, D=128, H=256, W=256] fp32
// out   [B, 2, D, H, W]: ch0 = copy, ch1 = sqrt(Gx^2+Gy^2+Gz^2 + 1e-8)
#define DIM_D 128
#define DIM_H 256
#define DIM_W 256
#define PLANE (DIM_H * DIM_W)
#define DCHUNK 32
#define NROWS 6                     // rows h0-1 .. h0+4 staged per plane
#define STAGE_F (NROWS * DIM_W)     // 1536 floats = 6 KB per buffer

typedef unsigned long long u64;

// ---- packed f32x2 helpers (sm_100+) ----
__device__ __forceinline__ u64 pk(float lo, float hi) {
    u64 r; asm("mov.b64 %0, {%1, %2};" : "=l"(r) : "f"(lo), "f"(hi)); return r;
}
__device__ __forceinline__ void upk(u64 a, float& lo, float& hi) {
    asm("mov.b64 {%0, %1}, %2;" : "=f"(lo), "=f"(hi) : "l"(a));
}
__device__ __forceinline__ u64 add2(u64 a, u64 b) {
    u64 r; asm("add.rn.f32x2 %0, %1, %2;" : "=l"(r) : "l"(a), "l"(b)); return r;
}
__device__ __forceinline__ u64 fma2(u64 a, u64 b, u64 c) {
    u64 r; asm("fma.rn.f32x2 %0, %1, %2, %3;" : "=l"(r) : "l"(a), "l"(b), "l"(c)); return r;
}
#define TWO2 0x4000000040000000ULL   // (2.0f, 2.0f)
#define NEG2 0xBF800000BF800000ULL   // (-1.0f, -1.0f)
#define EPS2 0x322BCC77322BCC77ULL   // (1e-8f, 1e-8f)

__device__ __forceinline__ void cp16(uint32_t saddr, const float* gp) {
    asm volatile("cp.async.ca.shared.global [%0], [%1], 16;" :: "r"(saddr), "l"(gp));
}
__device__ __forceinline__ void cp_commit() { asm volatile("cp.async.commit_group;"); }
__device__ __forceinline__ void cp_wait2()  { asm volatile("cp.async.wait_group 2;" ::: "memory"); }
__device__ __forceinline__ void cp_wait3()  { asm volatile("cp.async.wait_group 3;" ::: "memory"); }

// Fold one staged plane (smem) into separable partials, packed f32x2:
//   A = s_h*s_w(x) (Gz=d_d(A)); B = s_h*d_w(x) (Gx=s_d(B)); C = d_h*s_w(x) (Gy=s_d(C))
__device__ __forceinline__ void fold_smem(
    const float* __restrict__ sB, bool wl, bool wr,
    u64& A_lo, u64& A_hi, u64& B_lo, u64& B_hi, u64& C_lo, u64& C_hi,
    float4* cen)
{
#pragma unroll
    for (int r = 0; r < 3; r++) {
        const float* row = sB + r * DIM_W;
        const float4 c = *reinterpret_cast<const float4*>(row);
        const float xl = wl ? row[-1] : 0.f;
        const float xr = wr ? row[4]  : 0.f;
        if (r == 1 && cen) *cen = c;

        const u64 clo = pk(c.x, c.y), chi = pk(c.z, c.w);
        const u64 L = pk(xl, c.x);          // left-shifted pairs
        const u64 M = pk(c.y, c.z);         // middle (shared by L_hi / R_lo)
        const u64 R = pk(c.w, xr);          // right-shifted pairs
        const u64 ulo = fma2(clo, TWO2, add2(L, M));   // s_w
        const u64 uhi = fma2(chi, TWO2, add2(M, R));
        const u64 vlo = fma2(L, NEG2, M);               // d_w = R - L
        const u64 vhi = fma2(M, NEG2, R);

        if (r == 0) {
            A_lo = ulo; A_hi = uhi;
            B_lo = vlo; B_hi = vhi;
            C_lo = ulo; C_hi = uhi;                     // holds u0 until r==2
        } else if (r == 1) {
            A_lo = fma2(ulo, TWO2, A_lo); A_hi = fma2(uhi, TWO2, A_hi);
            B_lo = fma2(vlo, TWO2, B_lo); B_hi = fma2(vhi, TWO2, B_hi);
        } else {
            A_lo = add2(A_lo, ulo); A_hi = add2(A_hi, uhi);
            B_lo = add2(B_lo, vlo); B_hi = add2(B_hi, vhi);
            C_lo = fma2(C_lo, NEG2, ulo);               // u2 - u0
            C_hi = fma2(C_hi, NEG2, uhi);
        }
    }
}

__global__ void __launch_bounds__(256, 4)
sobel_edge_kernel(const float* __restrict__ img, float* __restrict__ out)
{
    __shared__ float sbuf[4][STAGE_F];

    const int tx  = threadIdx.x;           // 0..63 -> w (float4)
    const int ty  = threadIdx.y;           // 0..3  -> h row
    const int tid = tx + ty * 64;
    const int w0  = tx * 4;
    const int h0  = blockIdx.x * 4;
    const int h   = h0 + ty;
    const int d0  = blockIdx.y * DCHUNK;
    const int b   = blockIdx.z;

    const bool wl = w0 > 0, wr = (w0 + 4) < DIM_W;

    const float* gbase = img + (size_t)b * (DIM_D * PLANE);

    // staging: 384 16B chunks (6 rows x 64 float4) per plane, 256 threads
    const int r0 = tid >> 6,          c0 = tid & 63;
    const int r1 = (tid + 256) >> 6,  c1 = (tid + 256) & 63;
    const bool has1 = (tid + 256) < NROWS * 64;
    const int g0 = h0 - 1 + r0;
    const int g1 = h0 - 1 + r1;
    const bool gv0 = (g0 >= 0) && (g0 < DIM_H);
    const bool gv1 = (g1 >= 0) && (g1 < DIM_H);
    const float* gr0 = gbase + (size_t)g0 * DIM_W + c0 * 4;
    const float* gr1 = gbase + (size_t)g1 * DIM_W + c1 * 4;
    const uint32_t sB0 = (uint32_t)__cvta_generic_to_shared(&sbuf[0][0]);
    const uint32_t so0 = (uint32_t)(r0 * DIM_W + c0 * 4) * 4u;
    const uint32_t so1 = (uint32_t)(r1 * DIM_W + c1 * 4) * 4u;
    float* z0 = &sbuf[0][r0 * DIM_W + c0 * 4];
    float* z1 = &sbuf[0][r1 * DIM_W + c1 * 4];
    const float4 f4z = make_float4(0.f, 0.f, 0.f, 0.f);

    auto stage = [&](int s, int p, bool need) {
        if (need) {
            const bool pv = (p >= 0) && (p < DIM_D);
            const size_t poff = (size_t)p * PLANE;
            const uint32_t sbase = sB0 + (uint32_t)s * (STAGE_F * 4u);
            if (pv && gv0) cp16(sbase + so0, gr0 + poff);
            else *reinterpret_cast<float4*>(z0 + s * STAGE_F) = f4z;
            if (has1) {
                if (pv && gv1) cp16(sbase + so1, gr1 + poff);
                else *reinterpret_cast<float4*>(z1 + s * STAGE_F) = f4z;
            }
        }
        cp_commit();
    };

    float* o0 = out + (size_t)b * 2 * (DIM_D * PLANE)
              + (size_t)d0 * PLANE + (size_t)h * DIM_W + w0;
    float* o1 = o0 + (size_t)(DIM_D * PLANE);
    const float* sMy = &sbuf[0][ty * DIM_W + w0];

    // ring: planes (slot0 = d-1, slot1 = d, slot2 = d+1) packed f32x2
    u64 A0l, A0h, B0l, B0h, C0l, C0h;
    u64 A1l, A1h, B1l, B1h, C1l, C1h;
    u64 A2l, A2h, B2l, B2h, C2l, C2h;
    float4 cen;

    // prologue: stage planes d0-1..d0+2 into bufs 0..3 (prefetch depth 2)
    stage(0, d0 - 1, true);
    stage(1, d0,     true);
    stage(2, d0 + 1, true);
    stage(3, d0 + 2, true);
    cp_wait3();
    __syncthreads();
    fold_smem(sMy, wl, wr, A1l, A1h, B1l, B1h, C1l, C1h, nullptr);       // d0-1
    cp_wait2();
    __syncthreads();
    fold_smem(sMy + STAGE_F, wl, wr, A2l, A2h, B2l, B2h, C2l, C2h, &cen); // d0
    __stcs(reinterpret_cast<float4*>(o0), cen);                           // copy(d0)
    o0 += PLANE;

#pragma unroll 4
    for (int dd = 0; dd < DCHUNK; dd++) {
        // (1) stage plane d0+dd+3 into buf dd&3 (2 planes ahead of the fold)
        stage(dd & 3, d0 + dd + 3, dd < DCHUNK - 2);

        // (2) wait for plane d0+dd+1's group, sync, rotate, fold it
        cp_wait2();
        __syncthreads();
        A0l = A1l; A0h = A1h; B0l = B1l; B0h = B1h; C0l = C1l; C0h = C1h;
        A1l = A2l; A1h = A2h; B1l = B2l; B1h = B2h; C1l = C2l; C1h = C2h;
        fold_smem(&sbuf[(dd + 2) & 3][ty * DIM_W + w0], wl, wr,
                  A2l, A2h, B2l, B2h, C2l, C2h, &cen);
        if (dd < DCHUNK - 1) {                       // copy(d0+dd+1), chunk-owned
            __stcs(reinterpret_cast<float4*>(o0), cen);
        }
        o0 += PLANE;

        // (3) magnitude for plane d0+dd, packed
        const u64 gxl = fma2(B1l, TWO2, add2(B0l, B2l));
        const u64 gxh = fma2(B1h, TWO2, add2(B0h, B2h));
        const u64 gyl = fma2(C1l, TWO2, add2(C0l, C2l));
        const u64 gyh = fma2(C1h, TWO2, add2(C0h, C2h));
        const u64 gzl = fma2(A0l, NEG2, A2l);        // A2 - A0
        const u64 gzh = fma2(A0h, NEG2, A2h);
        const u64 ssl = fma2(gxl, gxl, fma2(gyl, gyl, fma2(gzl, gzl, EPS2)));
        const u64 ssh = fma2(gxh, gxh, fma2(gyh, gyh, fma2(gzh, gzh, EPS2)));
        float4 m;
        upk(ssl, m.x, m.y);
        upk(ssh, m.z, m.w);
        m.x = sqrtf(m.x); m.y = sqrtf(m.y); m.z = sqrtf(m.z); m.w = sqrtf(m.w);

        __stcs(reinterpret_cast<float4*>(o1), m);
        o1 += PLANE;
    }
}

extern "C" void kernel_launch(void* const* d_in, const int* in_sizes, int n_in,
                              void* d_out, int out_size)
{
    const float* img = (const float*)d_in[0];
    float* out = (float*)d_out;

    dim3 block(64, 4, 1);                        // 256 threads
    dim3 grid(DIM_H / 4, DIM_D / DCHUNK, 4);     // 64 x 4 x 4 = 1024 CTAs

    sobel_edge_kernel<<<grid, block>>>(img, out);
}

// round 9
// speedup vs baseline: 1.0762x; 1.0762x over previous
#include <cuda_runtime.h>
#include <cstdint>

// image [B=4, C=1, D=128, H=256, W=256] fp32
// out   [B, 2, D, H, W]: ch0 = copy, ch1 = sqrt(Gx^2+Gy^2+Gz^2 + 1e-8)
#define DIM_D 128
#define DIM_H 256
#define DIM_W 256
#define PLANE (DIM_H * DIM_W)
#define DCHUNK 64
#define NROWS 6                     // rows h0-1 .. h0+4 staged per plane
#define STAGE_F (NROWS * DIM_W)     // 1536 floats = 6 KB per buffer

__device__ __forceinline__ void cp16(uint32_t saddr, const float* gp) {
    asm volatile("cp.async.ca.shared.global [%0], [%1], 16;" :: "r"(saddr), "l"(gp));
}
__device__ __forceinline__ void cp_commit() { asm volatile("cp.async.commit_group;"); }
__device__ __forceinline__ void cp_wait1()  { asm volatile("cp.async.wait_group 1;" ::: "memory"); }
__device__ __forceinline__ void cp_wait2()  { asm volatile("cp.async.wait_group 2;" ::: "memory"); }

// Fold one staged plane (smem) into separable partials for this thread's row:
//   A = s_h*s_w(x) (Gz=d_d(A)); B = s_h*d_w(x) (Gx=s_d(B)); C = d_h*s_w(x) (Gy=s_d(C))
__device__ __forceinline__ void fold_smem(
    const float* __restrict__ sB,   // &sbuf[s][ty*DIM_W + w0]
    bool wl, bool wr,
    float4& A, float4& B, float4& C, float4* cen)
{
    A = make_float4(0.f, 0.f, 0.f, 0.f);
    B = A; C = A;
#pragma unroll
    for (int r = 0; r < 3; r++) {
        const float* row = sB + r * DIM_W;
        const float4 c = *reinterpret_cast<const float4*>(row);
        const float xl = wl ? row[-1] : 0.f;
        const float xr = wr ? row[4]  : 0.f;
        if (r == 1 && cen) *cen = c;

        float4 u, v;
        u.x = fmaf(2.f, c.x, xl  + c.y);
        u.y = fmaf(2.f, c.y, c.x + c.z);
        u.z = fmaf(2.f, c.z, c.y + c.w);
        u.w = fmaf(2.f, c.w, c.z + xr);
        v.x = c.y - xl;
        v.y = c.z - c.x;
        v.z = c.w - c.y;
        v.w = xr  - c.z;

        if (r == 1) {
            A.x = fmaf(2.f, u.x, A.x); A.y = fmaf(2.f, u.y, A.y);
            A.z = fmaf(2.f, u.z, A.z); A.w = fmaf(2.f, u.w, A.w);
            B.x = fmaf(2.f, v.x, B.x); B.y = fmaf(2.f, v.y, B.y);
            B.z = fmaf(2.f, v.z, B.z); B.w = fmaf(2.f, v.w, B.w);
        } else {
            const float dh = (r == 0) ? -1.f : 1.f;
            A.x += u.x; A.y += u.y; A.z += u.z; A.w += u.w;
            B.x += v.x; B.y += v.y; B.z += v.z; B.w += v.w;
            C.x = fmaf(dh, u.x, C.x); C.y = fmaf(dh, u.y, C.y);
            C.z = fmaf(dh, u.z, C.z); C.w = fmaf(dh, u.w, C.w);
        }
    }
}

__global__ void __launch_bounds__(256, 4)
sobel_edge_kernel(const float* __restrict__ img, float* __restrict__ out)
{
    __shared__ float sbuf[3][STAGE_F];

    const int tx  = threadIdx.x;           // 0..63 -> w (float4)
    const int ty  = threadIdx.y;           // 0..3  -> h row
    const int tid = tx + ty * 64;          // 0..255
    const int w0  = tx * 4;
    const int h0  = blockIdx.x * 4;
    const int h   = h0 + ty;
    const int d0  = blockIdx.y * DCHUNK;
    const int b   = blockIdx.z;

    const bool wl = w0 > 0, wr = (w0 + 4) < DIM_W;

    const float* gbase = img + (size_t)b * (DIM_D * PLANE);

    // --- staging assignment: 384 16B chunks (6 rows x 64 float4) per plane ---
    const int r0 = tid >> 6,          c0 = tid & 63;
    const int r1 = (tid + 256) >> 6,  c1 = (tid + 256) & 63;
    const bool has1 = (tid + 256) < NROWS * 64;
    const int g0 = h0 - 1 + r0;
    const int g1 = h0 - 1 + r1;
    const bool gv0 = (g0 >= 0) && (g0 < DIM_H);
    const bool gv1 = (g1 >= 0) && (g1 < DIM_H);
    const float* gr0 = gbase + (size_t)g0 * DIM_W + c0 * 4;   // + p*PLANE at use
    const float* gr1 = gbase + (size_t)g1 * DIM_W + c1 * 4;
    const uint32_t sB0 = (uint32_t)__cvta_generic_to_shared(&sbuf[0][0]);
    const uint32_t so0 = (uint32_t)(r0 * DIM_W + c0 * 4) * 4u;
    const uint32_t so1 = (uint32_t)(r1 * DIM_W + c1 * 4) * 4u;
    float* z0 = &sbuf[0][r0 * DIM_W + c0 * 4];  // generic ptrs for zero-fill
    float* z1 = &sbuf[0][r1 * DIM_W + c1 * 4];

    const float4 f4z = make_float4(0.f, 0.f, 0.f, 0.f);

    // Stage plane p into buffer s (zero-fills invalid plane/rows). Always commits.
    auto stage = [&](int s, int p, bool need) {
        if (need) {
            const bool pv = (p >= 0) && (p < DIM_D);
            const size_t poff = (size_t)p * PLANE;
            const uint32_t sbase = sB0 + (uint32_t)s * (STAGE_F * 4u);
            if (pv && gv0) cp16(sbase + so0, gr0 + poff);
            else *reinterpret_cast<float4*>(z0 + s * STAGE_F) = f4z;
            if (has1) {
                if (pv && gv1) cp16(sbase + so1, gr1 + poff);
                else *reinterpret_cast<float4*>(z1 + s * STAGE_F) = f4z;
            }
        }
        cp_commit();
    };

    // Output pointers
    float* o0 = out + (size_t)b * 2 * (DIM_D * PLANE)
              + (size_t)d0 * PLANE + (size_t)h * DIM_W + w0;   // copy ch, plane d0
    float* o1 = o0 + (size_t)(DIM_D * PLANE);                  // mag ch, plane d0
    const float* sMy = &sbuf[0][ty * DIM_W + w0];              // fold window, buf0

    float4 A0, B0, C0, A1, B1, C1, A2, B2, C2, cen;

    // --- prologue: stage planes d0-1, d0, d0+1 into bufs 0,1,2 ---
    stage(0, d0 - 1, true);
    stage(1, d0,     true);
    stage(2, d0 + 1, true);
    cp_wait2();
    __syncthreads();
    fold_smem(sMy, wl, wr, A1, B1, C1, nullptr);                  // plane d0-1
    cp_wait1();
    __syncthreads();
    fold_smem(sMy + STAGE_F, wl, wr, A2, B2, C2, &cen);           // plane d0
    __stcs(reinterpret_cast<float4*>(o0), cen);                   // copy(d0)
    o0 += PLANE;                                                  // -> plane d0+1

    int sw = 0;   // write buffer for this iter
    int sr = 2;   // read (fold) buffer for this iter

#pragma unroll 3
    for (int dd = 0; dd < DCHUNK; dd++) {
        // (1) stage plane d0+dd+2 into buf sw (not needed on last iter)
        stage(sw, d0 + dd + 2, dd < DCHUNK - 1);

        // (2) wait for plane d0+dd+1 (committed 2 groups ago), sync, fold it
        cp_wait1();
        __syncthreads();
        A0 = A1; B0 = B1; C0 = C1;
        A1 = A2; B1 = B2; C1 = C2;
        fold_smem(&sbuf[sr][ty * DIM_W + w0], wl, wr, A2, B2, C2, &cen);
        if (dd < DCHUNK - 1) {                    // copy(d0+dd+1) owned by this chunk
            __stcs(reinterpret_cast<float4*>(o0), cen);
        }
        o0 += PLANE;

        // (3) magnitude for plane d0+dd
        float4 gx, gy, gz, m;
        gx.x = fmaf(2.f, B1.x, B0.x + B2.x);
        gx.y = fmaf(2.f, B1.y, B0.y + B2.y);
        gx.z = fmaf(2.f, B1.z, B0.z + B2.z);
        gx.w = fmaf(2.f, B1.w, B0.w + B2.w);
        gy.x = fmaf(2.f, C1.x, C0.x + C2.x);
        gy.y = fmaf(2.f, C1.y, C0.y + C2.y);
        gy.z = fmaf(2.f, C1.z, C0.z + C2.z);
        gy.w = fmaf(2.f, C1.w, C0.w + C2.w);
        gz.x = A2.x - A0.x;
        gz.y = A2.y - A0.y;
        gz.z = A2.z - A0.z;
        gz.w = A2.w - A0.w;
        m.x = sqrtf(fmaf(gx.x, gx.x, fmaf(gy.x, gy.x, fmaf(gz.x, gz.x, 1e-8f))));
        m.y = sqrtf(fmaf(gx.y, gx.y, fmaf(gy.y, gy.y, fmaf(gz.y, gz.y, 1e-8f))));
        m.z = sqrtf(fmaf(gx.z, gx.z, fmaf(gy.z, gy.z, fmaf(gz.z, gz.z, 1e-8f))));
        m.w = sqrtf(fmaf(gx.w, gx.w, fmaf(gy.w, gy.w, fmaf(gz.w, gz.w, 1e-8f))));

        __stcs(reinterpret_cast<float4*>(o1), m);
        o1 += PLANE;

        // advance buffer ring (constant after unroll-3 copy propagation)
        sw = (sw == 2) ? 0 : sw + 1;
        sr = (sr == 2) ? 0 : sr + 1;
    }
}

extern "C" void kernel_launch(void* const* d_in, const int* in_sizes, int n_in,
                              void* d_out, int out_size)
{
    const float* img = (const float*)d_in[0];
    float* out = (float*)d_out;

    dim3 block(64, 4, 1);                        // 256 threads
    dim3 grid(DIM_H / 4, DIM_D / DCHUNK, 4);     // 64 x 2 x 4 = 512 CTAs

    sobel_edge_kernel<<<grid, block>>>(img, out);
}